// round 1
// baseline (speedup 1.0000x reference)
#include <cuda_runtime.h>

// Problem constants
#define Bq 4
#define Hq 256
#define Wq 256
#define Zq 64
#define ITER 8
#define EPS 1e-6

constexpr int N    = Bq * Hq * Wq * Zq;   // 16,777,216
constexpr int SAMP = Hq * Wq * Zq;        // 4,194,304 (2^22)
#define NT 256
constexpr int NBLK = N / 4 / NT;          // 16384 blocks, 4 elems/thread
// blocks per sample = SAMP / (NT*4) = 4096 = 2^12

// Scratch (device globals: no allocation allowed)
__device__ float g_x[N];
__device__ float g_r[N];
__device__ float g_p[N];
__device__ float g_w[N];

__device__ double   g_rho[ITER + 1][Bq];
__device__ double   g_eta[ITER][Bq];
__device__ double   g_loss;
__device__ unsigned g_max;

// ---------------------------------------------------------------------------
// helpers
// ---------------------------------------------------------------------------

__device__ __forceinline__ float4 ld4(const float* __restrict__ p) {
    return *reinterpret_cast<const float4*>(p);
}
__device__ __forceinline__ void st4(float* __restrict__ p, float4 v) {
    *reinterpret_cast<float4*>(p) = v;
}

// 7-point Laplacian on 4 consecutive z-elements starting at linear index i.
// center (the float4 at i) is returned through *cen.
__device__ __forceinline__ float4 stencil4(const float* __restrict__ in,
                                           int i, int z0, int wi, int h,
                                           float4* cen) {
    float4 c = ld4(in + i);
    *cen = c;
    float zl = (z0 != 0)  ? in[i - 1] : 0.f;   // bottom neighbor of lane 0
    float zr = (z0 != 60) ? in[i + 4] : 0.f;   // top neighbor of lane 3
    float4 z4 = make_float4(0.f, 0.f, 0.f, 0.f);
    float4 xm = (wi > 0)       ? ld4(in + i - Zq)        : z4;  // west
    float4 xp = (wi < Wq - 1)  ? ld4(in + i + Zq)        : z4;  // east
    float4 ym = (h  > 0)       ? ld4(in + i - Wq * Zq)   : z4;  // north
    float4 yp = (h  < Hq - 1)  ? ld4(in + i + Wq * Zq)   : z4;  // south
    float4 o;
    o.x = 6.f * c.x - xm.x - xp.x - ym.x - yp.x - zl  - c.y;
    o.y = 6.f * c.y - xm.y - xp.y - ym.y - yp.y - c.x - c.z;
    o.z = 6.f * c.z - xm.z - xp.z - ym.z - yp.z - c.y - c.w;
    o.w = 6.f * c.w - xm.w - xp.w - ym.w - yp.w - c.z - zr;
    return o;
}

// block-wide float sum -> one double atomicAdd
__device__ __forceinline__ void block_reduce_add(float val, double* target) {
    #pragma unroll
    for (int o = 16; o; o >>= 1)
        val += __shfl_xor_sync(0xffffffffu, val, o);
    __shared__ double sh[NT / 32];
    int lane = threadIdx.x & 31, wid = threadIdx.x >> 5;
    if (lane == 0) sh[wid] = (double)val;
    __syncthreads();
    if (threadIdx.x == 0) {
        double s = 0.0;
        #pragma unroll
        for (int k = 0; k < NT / 32; ++k) s += sh[k];
        atomicAdd(target, s);
    }
}

// block-wide float max (non-negative values) -> atomicMax on bit pattern
__device__ __forceinline__ void block_reduce_max(float val, unsigned* target) {
    #pragma unroll
    for (int o = 16; o; o >>= 1)
        val = fmaxf(val, __shfl_xor_sync(0xffffffffu, val, o));
    __shared__ float shm[NT / 32];
    int lane = threadIdx.x & 31, wid = threadIdx.x >> 5;
    if (lane == 0) shm[wid] = val;
    __syncthreads();
    if (threadIdx.x == 0) {
        float m = 0.f;
        #pragma unroll
        for (int k = 0; k < NT / 32; ++k) m = fmaxf(m, shm[k]);
        atomicMax(target, __float_as_uint(m));
    }
}

// ---------------------------------------------------------------------------
// kernels
// ---------------------------------------------------------------------------

__global__ void k_zero() {
    int t = threadIdx.x;
    if (t < (ITER + 1) * Bq) ((double*)g_rho)[t] = 0.0;
    if (t < ITER * Bq)       ((double*)g_eta)[t] = 0.0;
    if (t == 0) { g_loss = 0.0; g_max = 0u; }
}

// r = b - A*x_in ; p = r ; g_x = x_in ; rho0 += r.r
__global__ void k_init(const float* __restrict__ xin,
                       const float* __restrict__ bin) {
    int tid = blockIdx.x * NT + threadIdx.x;
    int i   = tid * 4;
    int z0  = i & 63;
    int wi  = (i >> 6) & 255;
    int h   = (i >> 14) & 255;
    int b   = i >> 22;

    float4 c;
    float4 ax = stencil4(xin, i, z0, wi, h, &c);
    float4 bb = ld4(bin + i);
    float4 r  = make_float4(bb.x - ax.x, bb.y - ax.y, bb.z - ax.z, bb.w - ax.w);
    st4(g_r + i, r);
    st4(g_p + i, r);
    st4(g_x + i, c);
    float d = r.x * r.x + r.y * r.y + r.z * r.z + r.w * r.w;
    block_reduce_add(d, &g_rho[0][b]);
}

// w = A*p ; eta[it] += p.w
__global__ void k_stencil_dot(int it) {
    int tid = blockIdx.x * NT + threadIdx.x;
    int i   = tid * 4;
    int z0  = i & 63;
    int wi  = (i >> 6) & 255;
    int h   = (i >> 14) & 255;
    int b   = i >> 22;

    float4 c;
    float4 w4 = stencil4(g_p, i, z0, wi, h, &c);
    st4(g_w + i, w4);
    float d = c.x * w4.x + c.y * w4.y + c.z * w4.z + c.w * w4.w;
    block_reduce_add(d, &g_eta[it][b]);
}

// alpha = rho/(eta+eps) ; x += alpha p ; r -= alpha w ; rho[it+1] += r.r
__global__ void k_update(int it) {
    int b = blockIdx.x >> 12;
    __shared__ float s_alpha;
    if (threadIdx.x == 0)
        s_alpha = (float)(g_rho[it][b] / (g_eta[it][b] + EPS));
    __syncthreads();
    float a = s_alpha;

    int i = (blockIdx.x * NT + threadIdx.x) * 4;
    float4 x = ld4(g_x + i), p = ld4(g_p + i);
    float4 r = ld4(g_r + i), w = ld4(g_w + i);
    x.x += a * p.x; x.y += a * p.y; x.z += a * p.z; x.w += a * p.w;
    r.x -= a * w.x; r.y -= a * w.y; r.z -= a * w.z; r.w -= a * w.w;
    st4(g_x + i, x);
    st4(g_r + i, r);
    float d = r.x * r.x + r.y * r.y + r.z * r.z + r.w * r.w;
    block_reduce_add(d, &g_rho[it + 1][b]);
}

// beta = rho[it+1]/(rho[it]+eps) ; p = r + beta p
__global__ void k_pupdate(int it) {
    int b = blockIdx.x >> 12;
    __shared__ float s_beta;
    if (threadIdx.x == 0)
        s_beta = (float)(g_rho[it + 1][b] / (g_rho[it][b] + EPS));
    __syncthreads();
    float bt = s_beta;

    int i = (blockIdx.x * NT + threadIdx.x) * 4;
    float4 r = ld4(g_r + i), p = ld4(g_p + i);
    p.x = r.x + bt * p.x; p.y = r.y + bt * p.y;
    p.z = r.z + bt * p.z; p.w = r.w + bt * p.w;
    st4(g_p + i, p);
}

// write x to out[1..N], accumulate loss & max_error
__global__ void k_final(const float* __restrict__ ref,
                        float* __restrict__ out) {
    int i = (blockIdx.x * NT + threadIdx.x) * 4;
    float4 x  = ld4(g_x + i);
    float4 rf = ld4(ref + i);
    // out+1 breaks 16B alignment -> scalar stores
    out[1 + i + 0] = x.x;
    out[1 + i + 1] = x.y;
    out[1 + i + 2] = x.z;
    out[1 + i + 3] = x.w;
    float dx = x.x - rf.x, dy = x.y - rf.y, dz = x.z - rf.z, dw = x.w - rf.w;
    float ss = dx * dx + dy * dy + dz * dz + dw * dw;
    float mx = fmaxf(fmaxf(fabsf(dx), fabsf(dy)), fmaxf(fabsf(dz), fabsf(dw)));
    block_reduce_add(ss, &g_loss);
    block_reduce_max(mx, &g_max);
}

__global__ void k_writeout(float* __restrict__ out) {
    out[0] = (float)(g_loss / (double)N);
    out[N + 1] = __uint_as_float(g_max);
    double s = 0.0;
    #pragma unroll
    for (int b = 0; b < Bq; ++b) s += g_rho[ITER][b];
    out[N + 2] = (float)(s / (double)Bq);
}

// ---------------------------------------------------------------------------

extern "C" void kernel_launch(void* const* d_in, const int* in_sizes, int n_in,
                              void* d_out, int out_size) {
    const float* x   = (const float*)d_in[0];
    const float* b   = (const float*)d_in[1];
    const float* ref = (const float*)d_in[2];
    float* out = (float*)d_out;

    k_zero<<<1, 64>>>();
    k_init<<<NBLK, NT>>>(x, b);
    for (int it = 0; it < ITER; ++it) {
        k_stencil_dot<<<NBLK, NT>>>(it);
        k_update<<<NBLK, NT>>>(it);
        if (it < ITER - 1) k_pupdate<<<NBLK, NT>>>(it);
    }
    k_final<<<NBLK, NT>>>(ref, out);
    k_writeout<<<1, 1>>>(out);
}

// round 2
// speedup vs baseline: 1.0493x; 1.0493x over previous
#include <cuda_runtime.h>

// Problem constants
#define Bq 4
#define Hq 256
#define Wq 256
#define Zq 64
#define ITER 8
#define EPS 1e-6

constexpr int N    = Bq * Hq * Wq * Zq;   // 16,777,216
#define NT 256
constexpr int NBLK = N / 4 / NT;          // 16384 blocks, 4 elems/thread
// blocks per sample = 4096 = 2^12

// Scratch (device globals: allocation is forbidden)
__device__ float g_x[N];
__device__ float g_r[N];
__device__ float g_pa[N];   // ping-pong p buffers
__device__ float g_pb[N];

__device__ double   g_rho[ITER + 1][Bq];
__device__ double   g_eta[ITER][Bq];
__device__ double   g_loss;
__device__ unsigned g_max;

// ---------------------------------------------------------------------------
// helpers
// ---------------------------------------------------------------------------

__device__ __forceinline__ float4 ld4(const float* __restrict__ p) {
    return *reinterpret_cast<const float4*>(p);
}
__device__ __forceinline__ void st4(float* __restrict__ p, float4 v) {
    *reinterpret_cast<float4*>(p) = v;
}

// 7-point Laplacian on 4 consecutive z-elements at linear index i.
// center float4 returned via *cen.
__device__ __forceinline__ float4 stencil4(const float* __restrict__ in,
                                           int i, int z0, int wi, int h,
                                           float4* cen) {
    float4 c = ld4(in + i);
    *cen = c;
    float zl = (z0 != 0)  ? in[i - 1] : 0.f;
    float zr = (z0 != 60) ? in[i + 4] : 0.f;
    float4 z4 = make_float4(0.f, 0.f, 0.f, 0.f);
    float4 xm = (wi > 0)      ? ld4(in + i - Zq)      : z4;
    float4 xp = (wi < Wq - 1) ? ld4(in + i + Zq)      : z4;
    float4 ym = (h  > 0)      ? ld4(in + i - Wq * Zq) : z4;
    float4 yp = (h  < Hq - 1) ? ld4(in + i + Wq * Zq) : z4;
    float4 o;
    o.x = 6.f * c.x - xm.x - xp.x - ym.x - yp.x - zl  - c.y;
    o.y = 6.f * c.y - xm.y - xp.y - ym.y - yp.y - c.x - c.z;
    o.z = 6.f * c.z - xm.z - xp.z - ym.z - yp.z - c.y - c.w;
    o.w = 6.f * c.w - xm.w - xp.w - ym.w - yp.w - c.z - zr;
    return o;
}

__device__ __forceinline__ void block_reduce_add(float val, double* target) {
    #pragma unroll
    for (int o = 16; o; o >>= 1)
        val += __shfl_xor_sync(0xffffffffu, val, o);
    __shared__ double sh[NT / 32];
    int lane = threadIdx.x & 31, wid = threadIdx.x >> 5;
    if (lane == 0) sh[wid] = (double)val;
    __syncthreads();
    if (threadIdx.x == 0) {
        double s = 0.0;
        #pragma unroll
        for (int k = 0; k < NT / 32; ++k) s += sh[k];
        atomicAdd(target, s);
    }
}

__device__ __forceinline__ void block_reduce_max(float val, unsigned* target) {
    #pragma unroll
    for (int o = 16; o; o >>= 1)
        val = fmaxf(val, __shfl_xor_sync(0xffffffffu, val, o));
    __shared__ float shm[NT / 32];
    int lane = threadIdx.x & 31, wid = threadIdx.x >> 5;
    if (lane == 0) shm[wid] = val;
    __syncthreads();
    if (threadIdx.x == 0) {
        float m = 0.f;
        #pragma unroll
        for (int k = 0; k < NT / 32; ++k) m = fmaxf(m, shm[k]);
        atomicMax(target, __float_as_uint(m));
    }
}

__device__ __forceinline__ void decode(int tid, int& i, int& z0, int& wi,
                                       int& h, int& b) {
    i  = tid * 4;
    z0 = i & 63;
    wi = (i >> 6) & 255;
    h  = (i >> 14) & 255;
    b  = i >> 22;
}

// p buffer for iteration it
__device__ __forceinline__ float* pbuf(int it) {
    return (it & 1) ? g_pb : g_pa;
}

// ---------------------------------------------------------------------------
// kernels
// ---------------------------------------------------------------------------

__global__ void k_zero() {
    int t = threadIdx.x;
    if (t < (ITER + 1) * Bq) ((double*)g_rho)[t] = 0.0;
    if (t < ITER * Bq)       ((double*)g_eta)[t] = 0.0;
    if (t == 0) { g_loss = 0.0; g_max = 0u; }
}

// r = b - A*x0 ; p0 = r ; rho0 += r.r       (no x copy — U(0) reads x0 input)
__global__ void k_init(const float* __restrict__ xin,
                       const float* __restrict__ bin) {
    int i, z0, wi, h, b;
    decode(blockIdx.x * NT + threadIdx.x, i, z0, wi, h, b);
    float4 c;
    float4 ax = stencil4(xin, i, z0, wi, h, &c);
    float4 bb = ld4(bin + i);
    float4 r  = make_float4(bb.x - ax.x, bb.y - ax.y, bb.z - ax.z, bb.w - ax.w);
    st4(g_r + i, r);
    st4(g_pa + i, r);
    float d = r.x * r.x + r.y * r.y + r.z * r.z + r.w * r.w;
    block_reduce_add(d, &g_rho[0][b]);
}

// eta kernel.
// FIRST: eta0 = p0 . A p0 (p0 already materialized, no write)
// else : beta = rho[it]/(rho[it-1]+eps);
//        p_new = r + beta*p_old  (written to pbuf(it))
//        A p_new = A r + beta * A p_old   (computed on the fly)
//        eta[it] += p_new . A p_new
template <bool FIRST>
__global__ void k_eta(int it) {
    int i, z0, wi, h, b;
    decode(blockIdx.x * NT + threadIdx.x, i, z0, wi, h, b);

    if (FIRST) {
        float4 c;
        float4 w = stencil4(g_pa, i, z0, wi, h, &c);
        float d = c.x * w.x + c.y * w.y + c.z * w.z + c.w * w.w;
        block_reduce_add(d, &g_eta[0][b]);
    } else {
        __shared__ float s_beta;
        if (threadIdx.x == 0)
            s_beta = (float)(g_rho[it][b] / (g_rho[it - 1][b] + EPS));
        __syncthreads();
        float bt = s_beta;

        const float* pold = pbuf(it - 1);
        float* pnew = pbuf(it);
        float4 cr, cp;
        float4 wr = stencil4(g_r, i, z0, wi, h, &cr);
        float4 wp = stencil4(pold, i, z0, wi, h, &cp);
        float4 pn = make_float4(cr.x + bt * cp.x, cr.y + bt * cp.y,
                                cr.z + bt * cp.z, cr.w + bt * cp.w);
        float4 w  = make_float4(wr.x + bt * wp.x, wr.y + bt * wp.y,
                                wr.z + bt * wp.z, wr.w + bt * wp.w);
        st4(pnew + i, pn);
        float d = pn.x * w.x + pn.y * w.y + pn.z * w.z + pn.w * w.w;
        block_reduce_add(d, &g_eta[it][b]);
    }
}

// update kernel. alpha = rho[it]/(eta[it]+eps)
//   w = A p (recomputed);  r_new = r - alpha*w ;  rho[it+1] += r_new.r_new
//   x_new = x_prev + alpha*p   (x_prev = input x0 when FIRST)
//   LAST: write x_new to out[1..N], fused loss / max_error vs ref;
//         r_new and x not stored (dead after last iteration).
template <bool FIRST, bool LAST>
__global__ void k_update(int it, const float* __restrict__ xin,
                         const float* __restrict__ ref,
                         float* __restrict__ out) {
    int i, z0, wi, h, b;
    decode(blockIdx.x * NT + threadIdx.x, i, z0, wi, h, b);

    __shared__ float s_alpha;
    if (threadIdx.x == 0)
        s_alpha = (float)(g_rho[it][b] / (g_eta[it][b] + EPS));
    __syncthreads();
    float a = s_alpha;

    const float* p = pbuf(it);
    float4 cp;
    float4 w = stencil4(p, i, z0, wi, h, &cp);
    float4 r = ld4(g_r + i);
    r.x -= a * w.x; r.y -= a * w.y; r.z -= a * w.z; r.w -= a * w.w;

    float4 x = FIRST ? ld4(xin + i) : ld4(g_x + i);
    x.x += a * cp.x; x.y += a * cp.y; x.z += a * cp.z; x.w += a * cp.w;

    if (!LAST) {
        st4(g_r + i, r);
        st4(g_x + i, x);
    } else {
        out[1 + i + 0] = x.x;
        out[1 + i + 1] = x.y;
        out[1 + i + 2] = x.z;
        out[1 + i + 3] = x.w;
        float4 rf = ld4(ref + i);
        float dx = x.x - rf.x, dy = x.y - rf.y;
        float dz = x.z - rf.z, dw = x.w - rf.w;
        float ss = dx * dx + dy * dy + dz * dz + dw * dw;
        float mx = fmaxf(fmaxf(fabsf(dx), fabsf(dy)),
                         fmaxf(fabsf(dz), fabsf(dw)));
        block_reduce_add(ss, &g_loss);
        block_reduce_max(mx, &g_max);
    }
    float d = r.x * r.x + r.y * r.y + r.z * r.z + r.w * r.w;
    block_reduce_add(d, &g_rho[it + 1][b]);
}

__global__ void k_writeout(float* __restrict__ out) {
    out[0] = (float)(g_loss / (double)N);
    out[N + 1] = __uint_as_float(g_max);
    double s = 0.0;
    #pragma unroll
    for (int b = 0; b < Bq; ++b) s += g_rho[ITER][b];
    out[N + 2] = (float)(s / (double)Bq);
}

// ---------------------------------------------------------------------------

extern "C" void kernel_launch(void* const* d_in, const int* in_sizes, int n_in,
                              void* d_out, int out_size) {
    const float* x   = (const float*)d_in[0];
    const float* b   = (const float*)d_in[1];
    const float* ref = (const float*)d_in[2];
    float* out = (float*)d_out;

    k_zero<<<1, 64>>>();
    k_init<<<NBLK, NT>>>(x, b);

    k_eta<true><<<NBLK, NT>>>(0);
    k_update<true, false><<<NBLK, NT>>>(0, x, nullptr, nullptr);

    for (int it = 1; it < ITER - 1; ++it) {
        k_eta<false><<<NBLK, NT>>>(it);
        k_update<false, false><<<NBLK, NT>>>(it, nullptr, nullptr, nullptr);
    }

    k_eta<false><<<NBLK, NT>>>(ITER - 1);
    k_update<false, true><<<NBLK, NT>>>(ITER - 1, nullptr, ref, out);

    k_writeout<<<1, 1>>>(out);
}

// round 3
// speedup vs baseline: 1.0743x; 1.0238x over previous
#include <cuda_runtime.h>

// Problem constants
#define Bq 4
#define Hq 256
#define Wq 256
#define Zq 64
#define ITER 8
#define EPS 1e-6

constexpr int N    = Bq * Hq * Wq * Zq;   // 16,777,216
#define NT 256
constexpr int NBLK = N / 4 / NT;          // 16384 blocks, 4 elems/thread
// blocks per sample = 4096 = 2^12

// Scratch (device globals: allocation is forbidden)
__device__ float g_x[N];
__device__ float g_r[N];
__device__ float g_pa[N];   // ping-pong p buffers
__device__ float g_pb[N];

__device__ double   g_rho[ITER + 1][Bq];
__device__ double   g_eta[ITER][Bq];
__device__ double   g_loss;
__device__ unsigned g_max;

// ---------------------------------------------------------------------------
// helpers
// ---------------------------------------------------------------------------

__device__ __forceinline__ float4 ld4(const float* __restrict__ p) {
    return *reinterpret_cast<const float4*>(p);
}
__device__ __forceinline__ void st4(float* __restrict__ p, float4 v) {
    *reinterpret_cast<float4*>(p) = v;
}

// 7-point Laplacian on 4 consecutive z-elements at linear index i.
// z-neighbors come from adjacent lanes via shuffle (16 lanes tile one z-line;
// line boundaries coincide with the z0 predicates). center returned via *cen.
__device__ __forceinline__ float4 stencil4(const float* __restrict__ in,
                                           int i, int z0, int wi, int h,
                                           float4* cen) {
    float4 c = ld4(in + i);
    *cen = c;
    float zl = __shfl_up_sync(0xffffffffu, c.w, 1);
    float zr = __shfl_down_sync(0xffffffffu, c.x, 1);
    if (z0 == 0)  zl = 0.f;
    if (z0 == 60) zr = 0.f;
    float4 z4 = make_float4(0.f, 0.f, 0.f, 0.f);
    float4 xm = (wi > 0)      ? ld4(in + i - Zq)      : z4;
    float4 xp = (wi < Wq - 1) ? ld4(in + i + Zq)      : z4;
    float4 ym = (h  > 0)      ? ld4(in + i - Wq * Zq) : z4;
    float4 yp = (h  < Hq - 1) ? ld4(in + i + Wq * Zq) : z4;
    float4 o;
    o.x = 6.f * c.x - xm.x - xp.x - ym.x - yp.x - zl  - c.y;
    o.y = 6.f * c.y - xm.y - xp.y - ym.y - yp.y - c.x - c.z;
    o.z = 6.f * c.z - xm.z - xp.z - ym.z - yp.z - c.y - c.w;
    o.w = 6.f * c.w - xm.w - xp.w - ym.w - yp.w - c.z - zr;
    return o;
}

__device__ __forceinline__ void block_reduce_add(float val, double* target) {
    #pragma unroll
    for (int o = 16; o; o >>= 1)
        val += __shfl_xor_sync(0xffffffffu, val, o);
    __shared__ double sh[NT / 32];
    int lane = threadIdx.x & 31, wid = threadIdx.x >> 5;
    if (lane == 0) sh[wid] = (double)val;
    __syncthreads();
    if (threadIdx.x == 0) {
        double s = 0.0;
        #pragma unroll
        for (int k = 0; k < NT / 32; ++k) s += sh[k];
        atomicAdd(target, s);
    }
}

__device__ __forceinline__ void block_reduce_max(float val, unsigned* target) {
    #pragma unroll
    for (int o = 16; o; o >>= 1)
        val = fmaxf(val, __shfl_xor_sync(0xffffffffu, val, o));
    __shared__ float shm[NT / 32];
    int lane = threadIdx.x & 31, wid = threadIdx.x >> 5;
    if (lane == 0) shm[wid] = val;
    __syncthreads();
    if (threadIdx.x == 0) {
        float m = 0.f;
        #pragma unroll
        for (int k = 0; k < NT / 32; ++k) m = fmaxf(m, shm[k]);
        atomicMax(target, __float_as_uint(m));
    }
}

__device__ __forceinline__ void decode(int tid, int& i, int& z0, int& wi,
                                       int& h, int& b) {
    i  = tid * 4;
    z0 = i & 63;
    wi = (i >> 6) & 255;
    h  = (i >> 14) & 255;
    b  = i >> 22;
}

// p buffer for iteration it
__device__ __forceinline__ float* pbuf(int it) {
    return (it & 1) ? g_pb : g_pa;
}

// ---------------------------------------------------------------------------
// kernels
// ---------------------------------------------------------------------------

__global__ void k_zero() {
    int t = threadIdx.x;
    if (t < (ITER + 1) * Bq) ((double*)g_rho)[t] = 0.0;
    if (t < ITER * Bq)       ((double*)g_eta)[t] = 0.0;
    if (t == 0) { g_loss = 0.0; g_max = 0u; }
}

// r = b - A*x0 ; p0 = r ; rho0 += r.r       (no x copy — U(0) reads x0 input)
__global__ void __launch_bounds__(NT, 8)
k_init(const float* __restrict__ xin, const float* __restrict__ bin) {
    int i, z0, wi, h, b;
    decode(blockIdx.x * NT + threadIdx.x, i, z0, wi, h, b);
    float4 c;
    float4 ax = stencil4(xin, i, z0, wi, h, &c);
    float4 bb = ld4(bin + i);
    float4 r  = make_float4(bb.x - ax.x, bb.y - ax.y, bb.z - ax.z, bb.w - ax.w);
    st4(g_r + i, r);
    st4(g_pa + i, r);
    float d = r.x * r.x + r.y * r.y + r.z * r.z + r.w * r.w;
    block_reduce_add(d, &g_rho[0][b]);
}

// eta kernel.
// FIRST: eta0 = p0 . A p0 (p0 already materialized, no write)
// else : beta = rho[it]/(rho[it-1]+eps);
//        p_new = r + beta*p_old  (written to pbuf(it))
//        A p_new = A r + beta * A p_old   (computed on the fly)
//        eta[it] += p_new . A p_new
template <bool FIRST>
__global__ void __launch_bounds__(NT, 8)
k_eta(int it) {
    int i, z0, wi, h, b;
    decode(blockIdx.x * NT + threadIdx.x, i, z0, wi, h, b);

    if (FIRST) {
        float4 c;
        float4 w = stencil4(g_pa, i, z0, wi, h, &c);
        float d = c.x * w.x + c.y * w.y + c.z * w.z + c.w * w.w;
        block_reduce_add(d, &g_eta[0][b]);
    } else {
        __shared__ float s_beta;
        if (threadIdx.x == 0)
            s_beta = (float)(g_rho[it][b] / (g_rho[it - 1][b] + EPS));
        __syncthreads();
        float bt = s_beta;

        const float* pold = pbuf(it - 1);
        float* pnew = pbuf(it);
        float4 cr, cp;
        float4 wr = stencil4(g_r, i, z0, wi, h, &cr);
        float4 wp = stencil4(pold, i, z0, wi, h, &cp);
        float4 pn = make_float4(cr.x + bt * cp.x, cr.y + bt * cp.y,
                                cr.z + bt * cp.z, cr.w + bt * cp.w);
        float4 w  = make_float4(wr.x + bt * wp.x, wr.y + bt * wp.y,
                                wr.z + bt * wp.z, wr.w + bt * wp.w);
        st4(pnew + i, pn);
        float d = pn.x * w.x + pn.y * w.y + pn.z * w.z + pn.w * w.w;
        block_reduce_add(d, &g_eta[it][b]);
    }
}

// update kernel. alpha = rho[it]/(eta[it]+eps)
//   w = A p (recomputed);  r_new = r - alpha*w ;  rho[it+1] += r_new.r_new
//   x_new = x_prev + alpha*p   (x_prev = input x0 when FIRST)
//   LAST: write x_new to out[1..N], fused loss / max_error vs ref;
//         r_new and x not stored (dead after last iteration).
template <bool FIRST, bool LAST>
__global__ void __launch_bounds__(NT, 8)
k_update(int it, const float* __restrict__ xin,
         const float* __restrict__ ref, float* __restrict__ out) {
    int i, z0, wi, h, b;
    decode(blockIdx.x * NT + threadIdx.x, i, z0, wi, h, b);

    __shared__ float s_alpha;
    if (threadIdx.x == 0)
        s_alpha = (float)(g_rho[it][b] / (g_eta[it][b] + EPS));
    __syncthreads();
    float a = s_alpha;

    const float* p = pbuf(it);
    float4 cp;
    float4 w = stencil4(p, i, z0, wi, h, &cp);
    float4 r = ld4(g_r + i);
    r.x -= a * w.x; r.y -= a * w.y; r.z -= a * w.z; r.w -= a * w.w;

    float4 x = FIRST ? ld4(xin + i) : ld4(g_x + i);
    x.x += a * cp.x; x.y += a * cp.y; x.z += a * cp.z; x.w += a * cp.w;

    if (!LAST) {
        st4(g_r + i, r);
        st4(g_x + i, x);
    } else {
        out[1 + i + 0] = x.x;
        out[1 + i + 1] = x.y;
        out[1 + i + 2] = x.z;
        out[1 + i + 3] = x.w;
        float4 rf = ld4(ref + i);
        float dx = x.x - rf.x, dy = x.y - rf.y;
        float dz = x.z - rf.z, dw = x.w - rf.w;
        float ss = dx * dx + dy * dy + dz * dz + dw * dw;
        float mx = fmaxf(fmaxf(fabsf(dx), fabsf(dy)),
                         fmaxf(fabsf(dz), fabsf(dw)));
        block_reduce_add(ss, &g_loss);
        block_reduce_max(mx, &g_max);
    }
    float d = r.x * r.x + r.y * r.y + r.z * r.z + r.w * r.w;
    block_reduce_add(d, &g_rho[it + 1][b]);
}

__global__ void k_writeout(float* __restrict__ out) {
    out[0] = (float)(g_loss / (double)N);
    out[N + 1] = __uint_as_float(g_max);
    double s = 0.0;
    #pragma unroll
    for (int b = 0; b < Bq; ++b) s += g_rho[ITER][b];
    out[N + 2] = (float)(s / (double)Bq);
}

// ---------------------------------------------------------------------------

extern "C" void kernel_launch(void* const* d_in, const int* in_sizes, int n_in,
                              void* d_out, int out_size) {
    const float* x   = (const float*)d_in[0];
    const float* b   = (const float*)d_in[1];
    const float* ref = (const float*)d_in[2];
    float* out = (float*)d_out;

    k_zero<<<1, 64>>>();
    k_init<<<NBLK, NT>>>(x, b);

    k_eta<true><<<NBLK, NT>>>(0);
    k_update<true, false><<<NBLK, NT>>>(0, x, nullptr, nullptr);

    for (int it = 1; it < ITER - 1; ++it) {
        k_eta<false><<<NBLK, NT>>>(it);
        k_update<false, false><<<NBLK, NT>>>(it, nullptr, nullptr, nullptr);
    }

    k_eta<false><<<NBLK, NT>>>(ITER - 1);
    k_update<false, true><<<NBLK, NT>>>(ITER - 1, nullptr, ref, out);

    k_writeout<<<1, 1>>>(out);
}

// round 4
// speedup vs baseline: 1.1112x; 1.0343x over previous
#include <cuda_runtime.h>

// Problem constants
#define Bq 4
#define Hq 256
#define Wq 256
#define Zq 64
#define ITER 8
#define EPS 1e-6

constexpr int N    = Bq * Hq * Wq * Zq;   // 16,777,216
#define NT 256
constexpr int NBLK = N / 4 / NT;          // 16384 blocks, 4 elems/thread

// Scratch (device globals: allocation is forbidden)
__device__ float g_x[N];
__device__ float g_r[N];
__device__ float g_pa[N];   // ping-pong p buffers
__device__ float g_pb[N];

__device__ double   g_rho[ITER + 1][Bq];
__device__ double   g_eta[ITER][Bq];
__device__ double   g_loss;
__device__ unsigned g_max;

// ---------------------------------------------------------------------------
// helpers
// ---------------------------------------------------------------------------

__device__ __forceinline__ float4 ld4(const float* __restrict__ p) {
    return *reinterpret_cast<const float4*>(p);
}
__device__ __forceinline__ float4 ld4cs(const float* __restrict__ p) {
    return __ldcs(reinterpret_cast<const float4*>(p));
}
__device__ __forceinline__ void st4(float* __restrict__ p, float4 v) {
    *reinterpret_cast<float4*>(p) = v;
}
__device__ __forceinline__ void st4cs(float* __restrict__ p, float4 v) {
    __stcs(reinterpret_cast<float4*>(p), v);
}

// 7-point Laplacian on 4 consecutive z-elements at linear index i.
// z-neighbors from adjacent lanes via shuffle (16 lanes tile one z-line).
__device__ __forceinline__ float4 stencil4(const float* __restrict__ in,
                                           int i, int z0, int wi, int h,
                                           float4* cen) {
    float4 c = ld4(in + i);
    *cen = c;
    float zl = __shfl_up_sync(0xffffffffu, c.w, 1);
    float zr = __shfl_down_sync(0xffffffffu, c.x, 1);
    if (z0 == 0)  zl = 0.f;
    if (z0 == 60) zr = 0.f;
    float4 z4 = make_float4(0.f, 0.f, 0.f, 0.f);
    float4 xm = (wi > 0)      ? ld4(in + i - Zq)      : z4;
    float4 xp = (wi < Wq - 1) ? ld4(in + i + Zq)      : z4;
    float4 ym = (h  > 0)      ? ld4(in + i - Wq * Zq) : z4;
    float4 yp = (h  < Hq - 1) ? ld4(in + i + Wq * Zq) : z4;
    float4 o;
    o.x = 6.f * c.x - xm.x - xp.x - ym.x - yp.x - zl  - c.y;
    o.y = 6.f * c.y - xm.y - xp.y - ym.y - yp.y - c.x - c.z;
    o.z = 6.f * c.z - xm.z - xp.z - ym.z - yp.z - c.y - c.w;
    o.w = 6.f * c.w - xm.w - xp.w - ym.w - yp.w - c.z - zr;
    return o;
}

__device__ __forceinline__ void block_reduce_add(float val, double* target) {
    #pragma unroll
    for (int o = 16; o; o >>= 1)
        val += __shfl_xor_sync(0xffffffffu, val, o);
    __shared__ double sh[NT / 32];
    int lane = threadIdx.x & 31, wid = threadIdx.x >> 5;
    if (lane == 0) sh[wid] = (double)val;
    __syncthreads();
    if (threadIdx.x == 0) {
        double s = 0.0;
        #pragma unroll
        for (int k = 0; k < NT / 32; ++k) s += sh[k];
        atomicAdd(target, s);
    }
}

__device__ __forceinline__ void block_reduce_max(float val, unsigned* target) {
    #pragma unroll
    for (int o = 16; o; o >>= 1)
        val = fmaxf(val, __shfl_xor_sync(0xffffffffu, val, o));
    __shared__ float shm[NT / 32];
    int lane = threadIdx.x & 31, wid = threadIdx.x >> 5;
    if (lane == 0) shm[wid] = val;
    __syncthreads();
    if (threadIdx.x == 0) {
        float m = 0.f;
        #pragma unroll
        for (int k = 0; k < NT / 32; ++k) m = fmaxf(m, shm[k]);
        atomicMax(target, __float_as_uint(m));
    }
}

// REV: sweep blocks in descending order so the next kernel (ascending)
// consumes the freshest end of L2 first (zigzag cross-kernel reuse).
template <bool REV>
__device__ __forceinline__ void decode(int& i, int& z0, int& wi,
                                       int& h, int& b) {
    int blk = REV ? (NBLK - 1 - (int)blockIdx.x) : (int)blockIdx.x;
    int tid = blk * NT + threadIdx.x;
    i  = tid * 4;
    z0 = i & 63;
    wi = (i >> 6) & 255;
    h  = (i >> 14) & 255;
    b  = i >> 22;
}

__device__ __forceinline__ float* pbuf(int it) {
    return (it & 1) ? g_pb : g_pa;
}

// ---------------------------------------------------------------------------
// kernels
// ---------------------------------------------------------------------------

__global__ void k_zero() {
    int t = threadIdx.x;
    if (t < (ITER + 1) * Bq) ((double*)g_rho)[t] = 0.0;
    if (t < ITER * Bq)       ((double*)g_eta)[t] = 0.0;
    if (t == 0) { g_loss = 0.0; g_max = 0u; }
}

// r = b - A*x0 ; p0 = r ; rho0 += r.r   (ascending sweep)
__global__ void __launch_bounds__(NT, 8)
k_init(const float* __restrict__ xin, const float* __restrict__ bin) {
    int i, z0, wi, h, b;
    decode<false>(i, z0, wi, h, b);
    float4 c;
    float4 ax = stencil4(xin, i, z0, wi, h, &c);
    float4 bb = ld4cs(bin + i);            // b: read exactly once
    float4 r  = make_float4(bb.x - ax.x, bb.y - ax.y, bb.z - ax.z, bb.w - ax.w);
    st4(g_r + i, r);
    st4(g_pa + i, r);
    float d = r.x * r.x + r.y * r.y + r.z * r.z + r.w * r.w;
    block_reduce_add(d, &g_rho[0][b]);
}

// eta kernel (descending sweep).
// FIRST: eta0 = p0 . A p0
// else : beta = rho[it]/(rho[it-1]+eps); p_new = r + beta*p_old;
//        A p_new = A r + beta A p_old;  eta[it] += p_new . A p_new
template <bool FIRST>
__global__ void __launch_bounds__(NT, 8)
k_eta(int it) {
    int i, z0, wi, h, b;
    decode<true>(i, z0, wi, h, b);

    if (FIRST) {
        float4 c;
        float4 w = stencil4(g_pa, i, z0, wi, h, &c);
        float d = c.x * w.x + c.y * w.y + c.z * w.z + c.w * w.w;
        block_reduce_add(d, &g_eta[0][b]);
    } else {
        __shared__ float s_beta;
        if (threadIdx.x == 0)
            s_beta = (float)(g_rho[it][b] / (g_rho[it - 1][b] + EPS));
        __syncthreads();
        float bt = s_beta;

        const float* pold = pbuf(it - 1);
        float* pnew = pbuf(it);
        float4 cr, cp;
        float4 wr = stencil4(g_r, i, z0, wi, h, &cr);
        float4 wp = stencil4(pold, i, z0, wi, h, &cp);
        float4 pn = make_float4(cr.x + bt * cp.x, cr.y + bt * cp.y,
                                cr.z + bt * cp.z, cr.w + bt * cp.w);
        float4 w  = make_float4(wr.x + bt * wp.x, wr.y + bt * wp.y,
                                wr.z + bt * wp.z, wr.w + bt * wp.w);
        st4(pnew + i, pn);
        float d = pn.x * w.x + pn.y * w.y + pn.z * w.z + pn.w * w.w;
        block_reduce_add(d, &g_eta[it][b]);
    }
}

// update kernel (ascending sweep). alpha = rho[it]/(eta[it]+eps)
//   r_new = r - alpha*A p ; rho[it+1] += r_new.r_new ; x_new = x + alpha*p
//   x carries no short-range reuse -> streaming hints keep it out of L2.
template <bool FIRST, bool LAST>
__global__ void __launch_bounds__(NT, 8)
k_update(int it, const float* __restrict__ xin,
         const float* __restrict__ ref, float* __restrict__ out) {
    int i, z0, wi, h, b;
    decode<false>(i, z0, wi, h, b);

    __shared__ float s_alpha;
    if (threadIdx.x == 0)
        s_alpha = (float)(g_rho[it][b] / (g_eta[it][b] + EPS));
    __syncthreads();
    float a = s_alpha;

    const float* p = pbuf(it);
    float4 cp;
    float4 w = stencil4(p, i, z0, wi, h, &cp);
    float4 r = ld4(g_r + i);
    r.x -= a * w.x; r.y -= a * w.y; r.z -= a * w.z; r.w -= a * w.w;

    float4 x = FIRST ? ld4cs(xin + i) : ld4cs(g_x + i);
    x.x += a * cp.x; x.y += a * cp.y; x.z += a * cp.z; x.w += a * cp.w;

    if (!LAST) {
        st4(g_r + i, r);
        st4cs(g_x + i, x);
    } else {
        __stcs(out + 1 + i + 0, x.x);
        __stcs(out + 1 + i + 1, x.y);
        __stcs(out + 1 + i + 2, x.z);
        __stcs(out + 1 + i + 3, x.w);
        float4 rf = ld4cs(ref + i);
        float dx = x.x - rf.x, dy = x.y - rf.y;
        float dz = x.z - rf.z, dw = x.w - rf.w;
        float ss = dx * dx + dy * dy + dz * dz + dw * dw;
        float mx = fmaxf(fmaxf(fabsf(dx), fabsf(dy)),
                         fmaxf(fabsf(dz), fabsf(dw)));
        block_reduce_add(ss, &g_loss);
        block_reduce_max(mx, &g_max);
    }
    float d = r.x * r.x + r.y * r.y + r.z * r.z + r.w * r.w;
    block_reduce_add(d, &g_rho[it + 1][b]);
}

__global__ void k_writeout(float* __restrict__ out) {
    out[0] = (float)(g_loss / (double)N);
    out[N + 1] = __uint_as_float(g_max);
    double s = 0.0;
    #pragma unroll
    for (int b = 0; b < Bq; ++b) s += g_rho[ITER][b];
    out[N + 2] = (float)(s / (double)Bq);
}

// ---------------------------------------------------------------------------

extern "C" void kernel_launch(void* const* d_in, const int* in_sizes, int n_in,
                              void* d_out, int out_size) {
    const float* x   = (const float*)d_in[0];
    const float* b   = (const float*)d_in[1];
    const float* ref = (const float*)d_in[2];
    float* out = (float*)d_out;

    k_zero<<<1, 64>>>();
    k_init<<<NBLK, NT>>>(x, b);

    k_eta<true><<<NBLK, NT>>>(0);
    k_update<true, false><<<NBLK, NT>>>(0, x, nullptr, nullptr);

    for (int it = 1; it < ITER - 1; ++it) {
        k_eta<false><<<NBLK, NT>>>(it);
        k_update<false, false><<<NBLK, NT>>>(it, nullptr, nullptr, nullptr);
    }

    k_eta<false><<<NBLK, NT>>>(ITER - 1);
    k_update<false, true><<<NBLK, NT>>>(ITER - 1, nullptr, ref, out);

    k_writeout<<<1, 1>>>(out);
}